// round 11
// baseline (speedup 1.0000x reference)
#include <cuda_runtime.h>
#include <cuda_bf16.h>

#define BATCH 8
#define CHANS 4
#define H 512
#define W 512
#define NPIX (BATCH * H * W)          // 2,097,152
#define NROWS (BATCH * H)             // 4096
#define LOSS_BLOCKS (BATCH * (H / 2)) // 2048

typedef unsigned long long u64;
#define FARPAIR 0x7f7f7f7f7f7f7f7full

// Scratch: per-pixel horizontal distances (byte pairs: fg, bg). One of the two
// is always 0; the other is the distance to the nearest opposite-class pixel.
__device__ uchar2 g_rcol[NPIX];
__device__ double g_bsum[LOSS_BLOCKS];

__device__ __forceinline__ unsigned mask8_of(int4 a, int4 b) {
    // labels are 0..3: gather low bytes (PRMT), then nonzero-per-byte bit trick
    unsigned ta = __byte_perm((unsigned)a.x, (unsigned)a.y, 0x4040);
    unsigned tb = __byte_perm((unsigned)a.z, (unsigned)a.w, 0x4040);
    unsigned ua = __byte_perm(ta, tb, 0x5410);
    unsigned tc = __byte_perm((unsigned)b.x, (unsigned)b.y, 0x4040);
    unsigned td = __byte_perm((unsigned)b.z, (unsigned)b.w, 0x4040);
    unsigned ub = __byte_perm(tc, td, 0x5410);
    ua = (ua | (ua >> 1)) & 0x01010101u;
    ub = (ub | (ub >> 1)) & 0x01010101u;
    return (((ua * 0x01020408u) >> 24) & 0xFu)
         | (((ub * 0x01020408u) >> 20) & 0xF0u);
}

// Per-row search: 8 pixels starting at byte gl, using padded row mask words.
__device__ __forceinline__ ulonglong2 search8(const unsigned* m32row, int gl) {
    const unsigned* base = m32row + (gl >> 2);
    unsigned m0 = base[0], m1 = base[1], m2 = base[2], m3 = base[3];
    unsigned e0 = m0 ^ __funnelshift_r(m0, m1, 1);
    unsigned e1 = m1 ^ __funnelshift_r(m1, m2, 1);
    unsigned e2 = m2 ^ __funnelshift_r(m2, m3, 1);
    // guard-induced fake transitions that could fake a distance <= 30:
    if (gl < 4)   e0 &= 0x7FFFFFFFu;      // padded bit 31 (guard|pixel0)
    if (gl >= 60) e1 &= 0x7FFFFFFFu;      // padded bit 543 (pixel511|guard)

    const int pb = (gl & 3) * 8;
    u64 out0 = 0ull, out1 = 0ull;
    #pragma unroll
    for (int j = 0; j < 8; ++j) {
        const int p = pb + j;
        unsigned R32 = __funnelshift_r(e1, e2, p);
        unsigned L32 = __funnelshift_r(e0, e1, p);
        int rd = __ffs((int)(R32 | 0x80000000u));    // 1..32 (32 = far)
        int ld = __clz((int)(L32 | 1u)) + 1;         // 1..32 (32 = far)
        unsigned e = (unsigned)min(rd, ld);
        unsigned pair = ((m1 >> p) & 1u) ? (e << 8) : e;
        if (j < 4) out0 |= (u64)pair << (16 * j);
        else       out1 |= (u64)pair << (16 * (j - 4));
    }
    return make_ulonglong2(out0, out1);
}

// ---------------------------------------------------------------------------
// Kernel 1: horizontal distances. 8 rows/block, 256 thr, 2 rows per thread
// (rows r and r+4) for 2x load MLP and two independent search chains.
// ---------------------------------------------------------------------------
__global__ void rowdist_kernel(const int4* __restrict__ yt4) {
    __shared__ unsigned m32[8][20];   // [0] guard, [1..16] mask, [17..19] guards
    const int tid = threadIdx.x;
    const int r  = tid >> 6;              // 0..3 -> rows r and r+4
    const int gl = tid & 63;              // byte index, pixels 8gl..8gl+7
    const int row0 = blockIdx.x * 8 + r;
    const int row1 = row0 + 4;

    const int4* p0 = yt4 + (size_t)row0 * 128 + gl * 2;
    const int4* p1 = yt4 + (size_t)row1 * 128 + gl * 2;
    int4 a0 = p0[0], b0 = p0[1], a1 = p1[0], b1 = p1[1];

    if (tid < 32) {                       // zero 4 guard words x 8 rows
        int rr = tid & 7, w = tid >> 3;   // w 0..3
        m32[rr][w == 0 ? 0 : 16 + w] = 0u;
    }
    unsigned m8a = mask8_of(a0, b0);
    unsigned m8b = mask8_of(a1, b1);
    ((unsigned char*)&m32[r][1])[gl]     = (unsigned char)m8a;
    ((unsigned char*)&m32[r + 4][1])[gl] = (unsigned char)m8b;
    __syncthreads();

    ulonglong2 o0 = search8(&m32[r][0], gl);
    ulonglong2 o1 = search8(&m32[r + 4][0], gl);
    ((ulonglong2*)g_rcol)[(size_t)row0 * 64 + gl] = o0;
    ((ulonglong2*)g_rcol)[(size_t)row1 * 64 + gl] = o1;
}

// ---------------------------------------------------------------------------
// Kernel 2: vertical combine (SIMD bytewise; first double-step prefetched and
// unconditional) + softmax + weighted SE + per-block reduction.
// 2 rows/block, 256 thr, 4 px/thread.
// ---------------------------------------------------------------------------
__global__ void __launch_bounds__(256, 8)
loss_kernel(const float4* __restrict__ logits4) {
    const int t = threadIdx.x & 127;      // x-quad 0..127
    const int r = threadIdx.x >> 7;       // row in block 0..1
    const int y = blockIdx.y * 2 + r;
    const int b = blockIdx.z;

    // ---- logits + self + first-ring taps: 9 independent loads in flight ----
    const float4* lp = logits4 + ((size_t)b * CHANS * H + y) * 128 + t;
    float4 L0 = lp[0];
    float4 L1 = lp[(size_t)H * 128];
    float4 L2 = lp[2 * (size_t)H * 128];
    float4 L3 = lp[3 * (size_t)H * 128];

    const u64* col = (const u64*)g_rcol + (size_t)b * H * 128 + t;
    u64 self = col[(size_t)y * 128];
    u64 up1 = (y - 1 >= 0) ? col[(size_t)(y - 1) * 128] : FARPAIR;
    u64 dn1 = (y + 1 <  H) ? col[(size_t)(y + 1) * 128] : FARPAIR;
    u64 up2 = (y - 2 >= 0) ? col[(size_t)(y - 2) * 128] : FARPAIR;
    u64 dn2 = (y + 2 <  H) ? col[(size_t)(y + 2) * 128] : FARPAIR;

    // ---- softmax while the tap loads fly ----
    float l0[4] = {L0.x, L0.y, L0.z, L0.w};
    float l1[4] = {L1.x, L1.y, L1.z, L1.w};
    float l2[4] = {L2.x, L2.y, L2.z, L2.w};
    float l3[4] = {L3.x, L3.y, L3.z, L3.w};
    float gp[4];
    #pragma unroll
    for (int k = 0; k < 4; ++k) {
        float hi  = fmaxf(l1[k], l2[k]);
        float lo  = fminf(l1[k], l2[k]);
        float aa  = fmaxf(hi, l3[k]);
        float sec = fminf(hi, l3[k]);
        float sum = 1.0f + __expf(lo - aa) + __expf(sec - aa) + __expf(l0[k] - aa);
        gp[k] = 1.0f / sum;
    }

    // ---- first double-step (d=1,2) unconditional with prefetched taps ----
    unsigned s0 = (unsigned)self;
    unsigned s1 = (unsigned)(self >> 32);
    {
        unsigned a0 = __vminu4((unsigned)up1, (unsigned)dn1);
        unsigned a1 = __vminu4((unsigned)(up1 >> 32), (unsigned)(dn1 >> 32));
        unsigned b0 = __vminu4((unsigned)up2, (unsigned)dn2);
        unsigned b1 = __vminu4((unsigned)(up2 >> 32), (unsigned)(dn2 >> 32));
        s0 = __vminu4(s0, __vminu4(__vmaxu4(a0, 0x01010101u), __vmaxu4(b0, 0x02020202u)));
        s1 = __vminu4(s1, __vminu4(__vmaxu4(a1, 0x01010101u), __vmaxu4(b1, 0x02020202u)));
    }

    // ---- remaining double-steps with early exit ----
    #pragma unroll 1
    for (int d = 3; d <= 29; d += 2) {
        unsigned mm = __vmaxu4(s0, s1);
        if (((mm + (128 - d) * 0x01010101u) & 0x80808080u) == 0u) break; // all <= d-1
        u64 u1 = (y - d     >= 0) ? col[(size_t)(y - d)     * 128] : FARPAIR;
        u64 d1 = (y + d     <  H) ? col[(size_t)(y + d)     * 128] : FARPAIR;
        u64 u2 = (y - d - 1 >= 0) ? col[(size_t)(y - d - 1) * 128] : FARPAIR;
        u64 d2 = (y + d + 1 <  H) ? col[(size_t)(y + d + 1) * 128] : FARPAIR;
        unsigned dd1 = (unsigned)d * 0x01010101u;
        unsigned dd2 = dd1 + 0x01010101u;
        unsigned a0 = __vminu4((unsigned)u1, (unsigned)d1);
        unsigned a1 = __vminu4((unsigned)(u1 >> 32), (unsigned)(d1 >> 32));
        unsigned b0 = __vminu4((unsigned)u2, (unsigned)d2);
        unsigned b1 = __vminu4((unsigned)(u2 >> 32), (unsigned)(d2 >> 32));
        s0 = __vminu4(s0, __vminu4(__vmaxu4(a0, dd1), __vmaxu4(b0, dd2)));
        s1 = __vminu4(s1, __vminu4(__vmaxu4(a1, dd1), __vmaxu4(b1, dd2)));
    }

    unsigned fgb[4], bgb[4];
    fgb[0] = s0 & 255u;         bgb[0] = (s0 >> 8) & 255u;
    fgb[1] = (s0 >> 16) & 255u; bgb[1] = s0 >> 24;
    fgb[2] = s1 & 255u;         bgb[2] = (s1 >> 8) & 255u;
    fgb[3] = (s1 >> 16) & 255u; bgb[3] = s1 >> 24;

    float v = 0.0f;
    #pragma unroll
    for (int k = 0; k < 4; ++k) {
        float dfg = (fgb[k] <= 30u) ? (float)fgb[k] : 200.0f;
        float dbg = (bgb[k] <= 30u) ? (float)bgb[k] : 200.0f;
        float wmap = dfg * dfg + dbg * dbg;
        float gt = (fgb[k] == 0u) ? 1.0f : 0.0f;
        float diff = gp[k] - gt;
        v += diff * diff * wmap;
    }

    // ---- deterministic block reduction (8 warps) ----
    #pragma unroll
    for (int o = 16; o > 0; o >>= 1) v += __shfl_down_sync(0xFFFFFFFFu, v, o);
    __shared__ float wsum[8];
    int lane = threadIdx.x & 31, wid = threadIdx.x >> 5;
    if (lane == 0) wsum[wid] = v;
    __syncthreads();
    if (threadIdx.x == 0) {
        double s = 0.0;
        #pragma unroll
        for (int i = 0; i < 8; ++i) s += (double)wsum[i];
        g_bsum[blockIdx.z * gridDim.y + blockIdx.y] = s;
    }
}

// Kernel 3: deterministic final reduction + mean.
__global__ void final_kernel(float* __restrict__ out) {
    __shared__ double sh[256];
    double s = 0.0;
    #pragma unroll
    for (int i = 0; i < LOSS_BLOCKS / 256; ++i)
        s += g_bsum[threadIdx.x + i * 256];
    sh[threadIdx.x] = s;
    __syncthreads();
    #pragma unroll
    for (int o = 128; o > 0; o >>= 1) {
        if (threadIdx.x < o) sh[threadIdx.x] += sh[threadIdx.x + o];
        __syncthreads();
    }
    if (threadIdx.x == 0) out[0] = (float)(sh[0] / (double)NPIX);
}

extern "C" void kernel_launch(void* const* d_in, const int* in_sizes, int n_in,
                              void* d_out, int out_size) {
    const float* logits = (const float*)d_in[0];
    const int*   y_true = (const int*)d_in[1];
    float*       out    = (float*)d_out;

    rowdist_kernel<<<NROWS / 8, 256>>>((const int4*)y_true);

    dim3 blk(256, 1, 1);
    dim3 grd(1, H / 2, BATCH);
    loss_kernel<<<grd, blk>>>((const float4*)logits);

    final_kernel<<<1, 256>>>(out);
}

// round 12
// speedup vs baseline: 1.0554x; 1.0554x over previous
#include <cuda_runtime.h>
#include <cuda_bf16.h>

#define BATCH 8
#define CHANS 4
#define H 512
#define W 512
#define NPIX (BATCH * H * W)          // 2,097,152
#define NROWS (BATCH * H)             // 4096
#define LOSS_BLOCKS (BATCH * (H / 4)) // 1024

typedef unsigned long long u64;
#define FARW 0x7f7f7f7fu

// Scratch: per-pixel horizontal distances (byte pairs: fg, bg). One of the two
// is always 0; the other is the distance to the nearest opposite-class pixel.
__device__ uchar2 g_rcol[NPIX];
__device__ double g_bsum[LOSS_BLOCKS];

// ---------------------------------------------------------------------------
// Kernel 1: horizontal distance to nearest opposite-class pixel. (R10 version)
// 4 rows/block (256 thr), 64 lanes/row, 8 px/lane; 32-bit funnel-shift search.
// ---------------------------------------------------------------------------
__global__ void rowdist_kernel(const int4* __restrict__ yt4) {
    __shared__ unsigned m32[4][20];   // [0] guard, [1..16] mask, [17..19] guards
    const int tid = threadIdx.x;
    const int r  = tid >> 6;              // row in block 0..3
    const int gl = tid & 63;              // byte index, pixels 8gl..8gl+7
    const int row = blockIdx.x * 4 + r;

    const int4* pp = yt4 + (size_t)row * 128 + gl * 2;
    int4 a = pp[0], b = pp[1];

    unsigned ta = __byte_perm((unsigned)a.x, (unsigned)a.y, 0x4040);
    unsigned tb = __byte_perm((unsigned)a.z, (unsigned)a.w, 0x4040);
    unsigned ua = __byte_perm(ta, tb, 0x5410);
    unsigned tc = __byte_perm((unsigned)b.x, (unsigned)b.y, 0x4040);
    unsigned td = __byte_perm((unsigned)b.z, (unsigned)b.w, 0x4040);
    unsigned ub = __byte_perm(tc, td, 0x5410);
    ua = (ua | (ua >> 1)) & 0x01010101u;
    ub = (ub | (ub >> 1)) & 0x01010101u;
    unsigned m8 = (((ua * 0x01020408u) >> 24) & 0xFu)
                | (((ub * 0x01020408u) >> 20) & 0xF0u);

    if (tid < 4) { m32[tid][0] = 0u; }
    if (tid >= 4 && tid < 16) { m32[tid & 3][17 + (tid >> 2) - 1] = 0u; }
    ((unsigned char*)&m32[r][1])[gl] = (unsigned char)m8;
    __syncthreads();

    const unsigned* base = &m32[r][gl >> 2];
    unsigned m0 = base[0], m1 = base[1], m2 = base[2], m3 = base[3];
    unsigned e0 = m0 ^ __funnelshift_r(m0, m1, 1);
    unsigned e1 = m1 ^ __funnelshift_r(m1, m2, 1);
    unsigned e2 = m2 ^ __funnelshift_r(m2, m3, 1);
    if (gl < 4)   e0 &= 0x7FFFFFFFu;      // fake transition guard|pixel0
    if (gl >= 60) e1 &= 0x7FFFFFFFu;      // fake transition pixel511|guard

    const int pb = (gl & 3) * 8;
    u64 out[2] = {0ull, 0ull};
    #pragma unroll
    for (int j = 0; j < 8; ++j) {
        const int p = pb + j;
        unsigned R32 = __funnelshift_r(e1, e2, p);
        unsigned L32 = __funnelshift_r(e0, e1, p);
        int rd = __ffs((int)(R32 | 0x80000000u));    // 1..32 (32 = far)
        int ld = __clz((int)(L32 | 1u)) + 1;         // 1..32 (32 = far)
        unsigned e = (unsigned)min(rd, ld);
        unsigned pair = ((m1 >> p) & 1u) ? (e << 8) : e;
        out[j >> 2] |= (u64)pair << (16 * (j & 3));
    }
    ((ulonglong2*)g_rcol)[(size_t)row * 64 + gl] = make_ulonglong2(out[0], out[1]);
}

__device__ __forceinline__ uint4 vmin44(uint4 a, uint4 b) {
    return make_uint4(__vminu4(a.x, b.x), __vminu4(a.y, b.y),
                      __vminu4(a.z, b.z), __vminu4(a.w, b.w));
}
__device__ __forceinline__ uint4 vmax4s(uint4 a, unsigned d) {
    return make_uint4(__vmaxu4(a.x, d), __vmaxu4(a.y, d),
                      __vmaxu4(a.z, d), __vmaxu4(a.w, d));
}

// ---------------------------------------------------------------------------
// Kernel 2: vertical combine + softmax + weighted SE + block reduction.
// 4 rows/block, 256 thr, 8 px/thread; taps are 16B uint4 loads.
// ---------------------------------------------------------------------------
__global__ void __launch_bounds__(256)
loss_kernel(const float4* __restrict__ logits4) {
    const int o = threadIdx.x & 63;       // x-octet 0..63 (pixels 8o..8o+7)
    const int r = threadIdx.x >> 6;       // row in block 0..3
    const int y = blockIdx.y * 4 + r;
    const int b = blockIdx.z;

    // ---- independent loads up front: self + 4 taps + 8 logits ----
    const uint4* col = (const uint4*)g_rcol + (size_t)b * H * 64 + o;
    uint4 self = col[(size_t)y * 64];
    const uint4 FARQ = make_uint4(FARW, FARW, FARW, FARW);
    uint4 up1 = (y - 1 >= 0) ? col[(size_t)(y - 1) * 64] : FARQ;
    uint4 dn1 = (y + 1 <  H) ? col[(size_t)(y + 1) * 64] : FARQ;
    uint4 up2 = (y - 2 >= 0) ? col[(size_t)(y - 2) * 64] : FARQ;
    uint4 dn2 = (y + 2 <  H) ? col[(size_t)(y + 2) * 64] : FARQ;

    const float4* lp = logits4 + ((size_t)b * CHANS * H + y) * 128 + o * 2;
    float4 La0 = lp[0];
    float4 La1 = lp[(size_t)H * 128];
    float4 La2 = lp[2 * (size_t)H * 128];
    float4 La3 = lp[3 * (size_t)H * 128];
    float4 Lb0 = lp[1];
    float4 Lb1 = lp[(size_t)H * 128 + 1];
    float4 Lb2 = lp[2 * (size_t)H * 128 + 1];
    float4 Lb3 = lp[3 * (size_t)H * 128 + 1];

    // ---- softmax for all 8 pixels while taps fly ----
    float gp[8];
    {
        float l0[8] = {La0.x, La0.y, La0.z, La0.w, Lb0.x, Lb0.y, Lb0.z, Lb0.w};
        float l1[8] = {La1.x, La1.y, La1.z, La1.w, Lb1.x, Lb1.y, Lb1.z, Lb1.w};
        float l2[8] = {La2.x, La2.y, La2.z, La2.w, Lb2.x, Lb2.y, Lb2.z, Lb2.w};
        float l3[8] = {La3.x, La3.y, La3.z, La3.w, Lb3.x, Lb3.y, Lb3.z, Lb3.w};
        #pragma unroll
        for (int k = 0; k < 8; ++k) {
            float hi  = fmaxf(l1[k], l2[k]);
            float lo  = fminf(l1[k], l2[k]);
            float aa  = fmaxf(hi, l3[k]);
            float sec = fminf(hi, l3[k]);
            float sum = 1.0f + __expf(lo - aa) + __expf(sec - aa) + __expf(l0[k] - aa);
            gp[k] = 1.0f / sum;
        }
    }

    // ---- first double-step (d=1,2) unconditional with prefetched taps ----
    uint4 s = self;
    s = vmin44(s, vmin44(vmax4s(vmin44(up1, dn1), 0x01010101u),
                         vmax4s(vmin44(up2, dn2), 0x02020202u)));

    // ---- remaining double-steps with early exit ----
    #pragma unroll 1
    for (int d = 3; d <= 29; d += 2) {
        unsigned mm = __vmaxu4(__vmaxu4(s.x, s.y), __vmaxu4(s.z, s.w));
        if (((mm + (128 - d) * 0x01010101u) & 0x80808080u) == 0u) break; // all <= d-1
        uint4 u1 = (y - d     >= 0) ? col[(size_t)(y - d)     * 64] : FARQ;
        uint4 d1 = (y + d     <  H) ? col[(size_t)(y + d)     * 64] : FARQ;
        uint4 u2 = (y - d - 1 >= 0) ? col[(size_t)(y - d - 1) * 64] : FARQ;
        uint4 d2 = (y + d + 1 <  H) ? col[(size_t)(y + d + 1) * 64] : FARQ;
        unsigned dd1 = (unsigned)d * 0x01010101u;
        unsigned dd2 = dd1 + 0x01010101u;
        s = vmin44(s, vmin44(vmax4s(vmin44(u1, d1), dd1),
                             vmax4s(vmin44(u2, d2), dd2)));
    }

    // ---- combine: integer wmap, fp32 error ----
    unsigned sw[4] = {s.x, s.y, s.z, s.w};
    float v = 0.0f;
    #pragma unroll
    for (int k = 0; k < 8; ++k) {
        unsigned w = sw[k >> 1] >> (16 * (k & 1));
        unsigned f = w & 255u;
        unsigned g = (w >> 8) & 255u;
        int df2 = (f <= 30u) ? (int)(f * f) : 40000;
        int dg2 = (g <= 30u) ? (int)(g * g) : 40000;
        float wmap = (float)(df2 + dg2);
        float gt = (f == 0u) ? 1.0f : 0.0f;
        float diff = gp[k] - gt;
        v += diff * diff * wmap;
    }

    // ---- deterministic block reduction (8 warps) ----
    #pragma unroll
    for (int oo = 16; oo > 0; oo >>= 1) v += __shfl_down_sync(0xFFFFFFFFu, v, oo);
    __shared__ float wsum[8];
    int lane = threadIdx.x & 31, wid = threadIdx.x >> 5;
    if (lane == 0) wsum[wid] = v;
    __syncthreads();
    if (threadIdx.x == 0) {
        double sd = 0.0;
        #pragma unroll
        for (int i = 0; i < 8; ++i) sd += (double)wsum[i];
        g_bsum[blockIdx.z * gridDim.y + blockIdx.y] = sd;
    }
}

// Kernel 3: deterministic final reduction + mean.
__global__ void final_kernel(float* __restrict__ out) {
    __shared__ double sh[256];
    double s = 0.0;
    #pragma unroll
    for (int i = 0; i < LOSS_BLOCKS / 256; ++i)
        s += g_bsum[threadIdx.x + i * 256];
    sh[threadIdx.x] = s;
    __syncthreads();
    #pragma unroll
    for (int o = 128; o > 0; o >>= 1) {
        if (threadIdx.x < o) sh[threadIdx.x] += sh[threadIdx.x + o];
        __syncthreads();
    }
    if (threadIdx.x == 0) out[0] = (float)(sh[0] / (double)NPIX);
}

extern "C" void kernel_launch(void* const* d_in, const int* in_sizes, int n_in,
                              void* d_out, int out_size) {
    const float* logits = (const float*)d_in[0];
    const int*   y_true = (const int*)d_in[1];
    float*       out    = (float*)d_out;

    rowdist_kernel<<<NROWS / 4, 256>>>((const int4*)y_true);

    dim3 blk(256, 1, 1);
    dim3 grd(1, H / 4, BATCH);
    loss_kernel<<<grd, blk>>>((const float4*)logits);

    final_kernel<<<1, 256>>>(out);
}